// round 7
// baseline (speedup 1.0000x reference)
#include <cuda_runtime.h>

// CRF forward recursion — multiplicative exp2-domain, one WARP per batch,
// ZERO shared memory: the p = exp2(alpha - M) vector lives entirely in
// registers, broadcast each step via warp shuffles (lane k owns columns
// 2k, 2k+1; pv_k = shfl(pn, k) is exactly the packed prev-pair needed).
// Per step: 64 SHFL.32 + 64 FFMA2 (fp32x2) + renorm side chain; no STS,
// no LDS, no syncwarp on the critical path.

#define FULLMASK 0xffffffffu
typedef unsigned long long ull;

__device__ __forceinline__ float ex2f_(float x){float r;asm("ex2.approx.f32 %0,%1;":"=f"(r):"f"(x));return r;}
__device__ __forceinline__ float lg2f_(float x){float r;asm("lg2.approx.f32 %0,%1;":"=f"(r):"f"(x));return r;}
__device__ __forceinline__ ull  pack2_(float lo,float hi){ull r;asm("mov.b64 %0,{%1,%2};":"=l"(r):"f"(lo),"f"(hi));return r;}
__device__ __forceinline__ void unpack2_(ull v,float&a,float&b){asm("mov.b64 {%0,%1},%2;":"=f"(a),"=f"(b):"l"(v));}
__device__ __forceinline__ float lo2_(ull v){float a,b;unpack2_(v,a,b);return a;}
__device__ __forceinline__ ull ffma2_(ull a,ull b,ull c){ull d;asm("fma.rn.f32x2 %0,%1,%2,%3;":"=l"(d):"l"(a),"l"(b),"l"(c));return d;}
__device__ __forceinline__ ull fadd2_(ull a,ull b){ull d;asm("add.rn.f32x2 %0,%1,%2;":"=l"(d):"l"(a),"l"(b));return d;}
__device__ __forceinline__ ull fmul2_(ull a,ull b){ull d;asm("mul.rn.f32x2 %0,%1,%2;":"=l"(d):"l"(a),"l"(b));return d;}

// Full 64-prev matvec for this lane's 2 columns; p broadcast via shuffles.
// Produces S0, S1 (must be declared by caller).
#define MATVEC_SHFL(PSRC)                                              \
    {                                                                  \
        ull A0 = 0, A1 = 0, B0 = 0, B1 = 0;                            \
        _Pragma("unroll")                                              \
        for (int k = 0; k < 32; k += 2) {                              \
            const ull pa = __shfl_sync(FULLMASK, (PSRC), k);           \
            const ull pb = __shfl_sync(FULLMASK, (PSRC), k + 1);       \
            A0 = ffma2_(pa, e0[k],     A0);                            \
            B0 = ffma2_(pa, e1[k],     B0);                            \
            A1 = ffma2_(pb, e0[k + 1], A1);                            \
            B1 = ffma2_(pb, e1[k + 1], B1);                            \
        }                                                              \
        const ull sa = fadd2_(A0, A1);                                 \
        const ull sb = fadd2_(B0, B1);                                 \
        float sa0, sa1, sb0, sb1;                                      \
        unpack2_(sa, sa0, sa1); unpack2_(sb, sb0, sb1);                \
        S0 = sa0 + sa1; S1 = sb0 + sb1;                                \
    }

__global__ __launch_bounds__(64, 1)
void crf_forward_kernel(const float* __restrict__ X,
                        const float* __restrict__ trans,
                        float* __restrict__ out,
                        int B, int T)
{
    constexpr float LOG2E = 1.4426950408889634f;
    constexpr float LN2   = 0.6931471805599453f;
    constexpr float NEG2  = -10000.0f * 1.4426950408889634f;

    const int tid  = threadIdx.x;
    const int w    = tid >> 5;
    const int lane = tid & 31;
    const int c0   = 2 * lane;
    const int c1   = c0 + 1;
    int b = blockIdx.x * 2 + w;
    if (b >= B) b = 0;                          // defensive (B even here)

    // E2 = exp2(trans * log2e), packed over prev pairs:
    //   e0[k] = (E2[2k][c0], E2[2k+1][c0]),  e1[k] = same for c1.
    // Column 0 (tag 'B', trans masked to -1e4) overridden to 1.0; the -1e4
    // is applied exactly via u[col0] = 0 each step and the NEG2 constant in
    // the epilogue. Row 1 (tag 'E', masked) underflows to exactly 0 in exp2
    // — identical to the reference's shifted-exp underflow.
    ull e0[32], e1[32];
#pragma unroll
    for (int k = 0; k < 32; k++) {
        const float t00 = trans[(2*k    ) * 64 + c0];
        const float t10 = trans[(2*k + 1) * 64 + c0];
        const float t01 = trans[(2*k    ) * 64 + c1];
        const float t11 = trans[(2*k + 1) * 64 + c1];
        e0[k] = pack2_((c0 == 0) ? 1.0f : ex2f_(t00 * LOG2E),
                       (c0 == 0) ? 1.0f : ex2f_(t10 * LOG2E));
        e1[k] = pack2_(ex2f_(t01 * LOG2E), ex2f_(t11 * LOG2E));
    }

    const float* __restrict__ xp = X + (size_t)b * T * 64 + c0;
    const float* xlast = xp + (size_t)(T - 1) * 64;

    // ---- step 0, peeled analytically: p_0 = (1,0,...,0) is one-hot, so
    //   p_1[c] = E2[0][c] * u_0[c],  u_0 = exp2(x_0 * log2e) (masked col 0).
    const float2 x0v = *(const float2*)xp;
    const ull u0 = pack2_((c0 == 0) ? 0.0f : ex2f_(x0v.x * LOG2E),
                          ex2f_(x0v.y * LOG2E));
    ull pn = fmul2_(pack2_(lo2_(e0[0]), lo2_(e1[0])), u0);  // p_1

    // x prefetch queue: xq0 = x_1, xq1 = x_2 (clamped for tiny T)
    const float* x1p = xp + 64;  if (x1p > xlast) x1p = xlast;
    const float* x2p = xp + 128; if (x2p > xlast) x2p = xlast;
    float2 xq0 = *(const float2*)x1p;
    float2 xq1 = *(const float2*)x2p;
    const float* xpre = xp + 192; if (xpre > xlast) xpre = xlast;

    float M = 0.0f;

    // ---- bodies t = 1 .. T-2: produce p_{t+1} from p_t (=pn), consume x_t.
#pragma unroll 1
    for (int t = 1; t <= T - 2; t++) {
        // renorm side chain: d = lg2(p_t[2]); u = exp2(x_t*log2e - d)
        const float p2 = __shfl_sync(FULLMASK, lo2_(pn), 1);  // lane1.lo = p[2]
        const float dn = lg2f_(p2);
        M += dn;
        float un0 = ex2f_(fmaf(xq0.x, LOG2E, -dn));
        float un1 = ex2f_(fmaf(xq0.y, LOG2E, -dn));
        if (c0 == 0) un0 = 0.0f;
        const ull u = pack2_(un0, un1);

        xq0 = xq1;
        xq1 = *(const float2*)xpre;
        xpre += 64; if (xpre > xlast) xpre = xlast;

        float S0, S1;
        MATVEC_SHFL(pn);
        pn = fmul2_(pack2_(S0, S1), u);
    }

    // ---- epilogue: S = p_{T-1} E; alpha_T = (lg2 S + x_{T-1}*log2e + M)*ln2.
    {
        float S0, S1;
        MATVEC_SHFL(pn);
        const float m0 = (c0 == 0) ? NEG2 : 0.0f;
        const float o0 = (lg2f_(S0) + xq0.x * LOG2E + m0 + M) * LN2;
        const float o1 = (lg2f_(S1) + xq0.y * LOG2E +      M) * LN2;
        *(float2*)&out[(size_t)b * 64 + c0] = make_float2(o0, o1);
    }
}

extern "C" void kernel_launch(void* const* d_in, const int* in_sizes, int n_in,
                              void* d_out, int out_size)
{
    const float* X     = (const float*)d_in[0];
    const float* trans = (const float*)d_in[1];
    float* out = (float*)d_out;

    const int B = out_size / 64;               // 256
    const int T = in_sizes[0] / (B * 64);      // 512

    const int blocks = (B + 1) / 2;            // 2 warps per CTA, 1 batch each
    crf_forward_kernel<<<blocks, 64>>>(X, trans, out, B, T);
}

// round 8
// speedup vs baseline: 1.9118x; 1.9118x over previous
#include <cuda_runtime.h>
#include <cuda_fp16.h>

// CRF forward recursion — multiplicative exp2-domain, one WARP per batch,
// fp16 matvec (HFMA2, rt=2, 2 MACs/instr) with fp32 control path.
// Each lane owns columns (2*lane, 2*lane+1). E2h = fp16(exp2(trans*log2e - 8))
// resident in 64 half2 registers; p stored as half2 in warp-private smem
// (satfinite convert), ONE __syncwarp per step. Renorm shift d = lg2(max of
// p over 4 sampled tags {2,3,34,35}) keeps the fp16 range safe; the 2^-8
// E-scaling is corrected by a constant +8*T at the end (M absorbs the rest).

#define FULLMASK 0xffffffffu

__device__ __forceinline__ float ex2f_(float x){float r;asm("ex2.approx.f32 %0,%1;":"=f"(r):"f"(x));return r;}
__device__ __forceinline__ float lg2f_(float x){float r;asm("lg2.approx.f32 %0,%1;":"=f"(r):"f"(x));return r;}
// d.hi = convert(hi), d.lo = convert(lo), saturating to +/-65504 (no inf)
__device__ __forceinline__ unsigned f22h2sat_(float hi, float lo){
    unsigned r; asm("cvt.rn.satfinite.f16x2.f32 %0,%1,%2;":"=r"(r):"f"(hi),"f"(lo)); return r;
}

// Full 64-prev fp16 matvec for this lane's 2 columns; p from smem buffer.
// Produces fp32 S0, S1 (declared by caller).
#define MATVEC_H(BUF)                                                   \
    {                                                                   \
        const uint4* __restrict__ pp = (const uint4*)pbuf[w][BUF];      \
        __half2 A0 = z2, A1 = z2, A2 = z2, A3 = z2;                     \
        __half2 B0 = z2, B1 = z2, B2 = z2, B3 = z2;                     \
        _Pragma("unroll")                                               \
        for (int k = 0; k < 8; k++) {                                   \
            const uint4 q = pp[k];            /* prevs 8k .. 8k+7 */    \
            const __half2 p0 = *(const __half2*)&q.x;                   \
            const __half2 p1 = *(const __half2*)&q.y;                   \
            const __half2 p2 = *(const __half2*)&q.z;                   \
            const __half2 p3 = *(const __half2*)&q.w;                   \
            A0 = __hfma2(p0, e0h[4*k+0], A0);                           \
            B0 = __hfma2(p0, e1h[4*k+0], B0);                           \
            A1 = __hfma2(p1, e0h[4*k+1], A1);                           \
            B1 = __hfma2(p1, e1h[4*k+1], B1);                           \
            A2 = __hfma2(p2, e0h[4*k+2], A2);                           \
            B2 = __hfma2(p2, e1h[4*k+2], B2);                           \
            A3 = __hfma2(p3, e0h[4*k+3], A3);                           \
            B3 = __hfma2(p3, e1h[4*k+3], B3);                           \
        }                                                               \
        const float2 fa0 = __half22float2(__hadd2(A0, A1));             \
        const float2 fa1 = __half22float2(__hadd2(A2, A3));             \
        const float2 fb0 = __half22float2(__hadd2(B0, B1));             \
        const float2 fb1 = __half22float2(__hadd2(B2, B3));             \
        S0 = (fa0.x + fa0.y) + (fa1.x + fa1.y);                         \
        S1 = (fb0.x + fb0.y) + (fb1.x + fb1.y);                         \
    }

// One mainloop step t>=1: side chain (d, u) from pnf (=p_t) + xq0 (=x_t),
// matvec from pbuf[BUF], produce p_{t+1}, publish, sync.
#define STEP(BUF)                                                       \
    {                                                                   \
        float v = fmaxf(pnf0, pnf1);                                    \
        v = fmaxf(v, __shfl_xor_sync(FULLMASK, v, 16));                 \
        const float pm = __shfl_sync(FULLMASK, v, 1); /* tags 2,3,34,35 */ \
        const float dn = lg2f_(pm);                                     \
        M += dn;                                                        \
        float un0 = ex2f_(fmaf(xq0.x, LOG2E, -dn));                     \
        float un1 = ex2f_(fmaf(xq0.y, LOG2E, -dn));                     \
        if (c0 == 0) un0 = 0.0f;                                        \
        xq0 = xq1;                                                      \
        xq1 = *(const float2*)xpre;                                     \
        xpre += 64; if (xpre > xlast) xpre = xlast;                     \
        float S0, S1;                                                   \
        MATVEC_H(BUF);                                                  \
        pnf0 = S0 * un0;                                                \
        pnf1 = S1 * un1;                                                \
        ((unsigned*)pbuf[w][(BUF) ^ 1])[lane] = f22h2sat_(pnf1, pnf0);  \
        __syncwarp();                                                   \
    }

__global__ __launch_bounds__(64, 1)
void crf_forward_kernel(const float* __restrict__ X,
                        const float* __restrict__ trans,
                        float* __restrict__ out,
                        int B, int T)
{
    constexpr float LOG2E = 1.4426950408889634f;
    constexpr float LN2   = 0.6931471805599453f;
    constexpr float NEG2  = -10000.0f * 1.4426950408889634f;
    constexpr float SCALE = 8.0f;                 // E2 pre-scaled by 2^-8

    const int tid  = threadIdx.x;
    const int w    = tid >> 5;
    const int lane = tid & 31;
    const int c0   = 2 * lane;
    const int c1   = c0 + 1;
    int b = blockIdx.x * 2 + w;
    if (b >= B) b = 0;                            // defensive (B even here)

    // p exchange: [warp][double-buffer][32 half2 words] (word l = tags 2l,2l+1)
    __shared__ __align__(16) __half2 pbuf[2][2][32];

    const __half2 z2 = __float2half2_rn(0.0f);

    // E2h[k] = fp16( exp2(trans[2k..2k+1][c] * log2e - SCALE) ).
    // Column 0 (tag 'B', trans masked -1e4) overridden to exp2(-SCALE): then
    // S[0] = 2^-SCALE * sum(p) and the -1e4 is applied exactly via u[0]=0 per
    // step and the NEG2 constant in the epilogue. Row 1 (tag 'E', masked)
    // becomes exactly 0 — matches the reference's shifted-exp underflow.
    __half2 e0h[32], e1h[32];
    const float escale = ex2f_(-SCALE);
#pragma unroll
    for (int k = 0; k < 32; k++) {
        const float t00 = trans[(2*k    ) * 64 + c0];
        const float t10 = trans[(2*k + 1) * 64 + c0];
        const float t01 = trans[(2*k    ) * 64 + c1];
        const float t11 = trans[(2*k + 1) * 64 + c1];
        const float f00 = (c0 == 0) ? escale : ex2f_(fmaf(t00, LOG2E, -SCALE));
        const float f10 = (c0 == 0) ? escale : ex2f_(fmaf(t10, LOG2E, -SCALE));
        e0h[k] = __floats2half2_rn(f00, f10);
        e1h[k] = __floats2half2_rn(ex2f_(fmaf(t01, LOG2E, -SCALE)),
                                   ex2f_(fmaf(t11, LOG2E, -SCALE)));
    }

    const float* __restrict__ xp = X + (size_t)b * T * 64 + c0;
    const float* xlast = xp + (size_t)(T - 1) * 64;

    // ---- step 0 peeled analytically: p_0 one-hot -> p_1[c] = E2h[0][c]*u_0[c]
    const float2 x0v = *(const float2*)xp;
    const float u00 = (c0 == 0) ? 0.0f : ex2f_(x0v.x * LOG2E);
    const float u01 = ex2f_(x0v.y * LOG2E);
    float pnf0 = __low2float(e0h[0]) * u00;       // p_1[c0] (scaled domain)
    float pnf1 = __low2float(e1h[0]) * u01;       // p_1[c1]
    ((unsigned*)pbuf[w][1])[lane] = f22h2sat_(pnf1, pnf0);
    __syncwarp();

    // x prefetch queue: xq0 = x_1, xq1 = x_2 (clamped for tiny T)
    const float* x1p = xp + 64;  if (x1p > xlast) x1p = xlast;
    const float* x2p = xp + 128; if (x2p > xlast) x2p = xlast;
    float2 xq0 = *(const float2*)x1p;
    float2 xq1 = *(const float2*)x2p;
    const float* xpre = xp + 192; if (xpre > xlast) xpre = xlast;

    float M = 0.0f;

    // ---- bodies t = 1 .. T-2, ping-pong unrolled x2
    const int npairs = (T - 2) >> 1;
#pragma unroll 1
    for (int it = 0; it < npairs; it++) {
        STEP(1);
        STEP(0);
    }
    int finbuf = 1;
    if ((T - 2) & 1) { STEP(1); finbuf = 0; }

    // ---- epilogue: S = p_{T-1} E2h;  alpha_T = (lg2 S + x*log2e + M + 8T)*ln2
    {
        float S0, S1;
        MATVEC_H(finbuf);
        const float corr = M + SCALE * (float)T;   // undo per-step 2^-8 scaling
        const float m0 = (c0 == 0) ? NEG2 : 0.0f;
        const float o0 = (lg2f_(S0) + xq0.x * LOG2E + m0 + corr) * LN2;
        const float o1 = (lg2f_(S1) + xq0.y * LOG2E +      corr) * LN2;
        *(float2*)&out[(size_t)b * 64 + c0] = make_float2(o0, o1);
    }
}

extern "C" void kernel_launch(void* const* d_in, const int* in_sizes, int n_in,
                              void* d_out, int out_size)
{
    const float* X     = (const float*)d_in[0];
    const float* trans = (const float*)d_in[1];
    float* out = (float*)d_out;

    const int B = out_size / 64;                  // 256
    const int T = in_sizes[0] / (B * 64);         // 512

    const int blocks = (B + 1) / 2;               // 2 warps per CTA, 1 batch each
    crf_forward_kernel<<<blocks, 64>>>(X, trans, out, B, T);
}